// round 9
// baseline (speedup 1.0000x reference)
#include <cuda_runtime.h>

#define BB 1024
#define TT 200

// Precomputed x-dependent halves:
// g_Xg[m][j] = b_gate[j] + sum_k X[m][k]*W_gate[k][j]   (j in [0,256))
// g_Xc[m][j] = b_cand[j] + sum_k X[m][k]*W_cand[k][j]   (j in [0,128))
__device__ float g_Xg[(size_t)BB * TT * 256];
__device__ float g_Xc[(size_t)BB * TT * 128];

typedef unsigned long long u64;

__device__ __forceinline__ u64 pack2(float a, float b) {
    u64 r; asm("mov.b64 %0,{%1,%2};" : "=l"(r) : "f"(a), "f"(b)); return r;
}
__device__ __forceinline__ u64 splat2(float a) { return pack2(a, a); }
__device__ __forceinline__ void fma2(u64& d, u64 a, u64 b) {
    asm("fma.rn.f32x2 %0,%1,%2,%0;" : "+l"(d) : "l"(a), "l"(b));
}
__device__ __forceinline__ float2 unpack2(u64 v) {
    float2 r; asm("mov.b64 {%0,%1},%2;" : "=f"(r.x), "=f"(r.y) : "l"(v)); return r;
}

__device__ __forceinline__ float sigmoid_f(float x) {
    return __fdividef(1.0f, 1.0f + __expf(-x));
}
__device__ __forceinline__ float tanh_f(float x) {
    return 1.0f - __fdividef(2.0f, __expf(2.0f * x) + 1.0f);
}

// ---------------------------------------------------------------------------
// Kernel A: Xg/Xc precompute GEMM with packed f32x2 FMA (measured 466us).
// Block tile 64(M) x 128(N), K=128; loops nt=0..2 reusing the X tile in smem.
// ---------------------------------------------------------------------------
__global__ __launch_bounds__(256, 1)
void precompute_kernel(const float* __restrict__ X,
                       const float* __restrict__ Wg,
                       const float* __restrict__ bg,
                       const float* __restrict__ Wc,
                       const float* __restrict__ bc)
{
    extern __shared__ float sm[];
    float* Xs = sm;              // [64][132] row-major, padded
    float* Ws = sm + 64 * 132;   // [128][128]

    const int tid = threadIdx.x;
    const int m0  = blockIdx.x * 64;

    #pragma unroll
    for (int i = 0; i < 8; i++) {
        int idx = tid + i * 256;
        int m   = idx >> 5;
        int k4  = idx & 31;
        float4 v = *(const float4*)&X[(size_t)(m0 + m) * 128 + k4 * 4];
        *(float4*)&Xs[m * 132 + k4 * 4] = v;
    }

    const int colg = tid & 31;
    const int rowg = tid >> 5;
    const int c0 = colg * 4;
    const int r0 = rowg * 8;

    for (int nt = 0; nt < 3; nt++) {
        __syncthreads();
        const float* Wsrc; int ldw, n0;
        if (nt < 2) { Wsrc = Wg; ldw = 256; n0 = nt * 128; }
        else        { Wsrc = Wc; ldw = 128; n0 = 0; }
        #pragma unroll
        for (int i = 0; i < 16; i++) {
            int idx = tid + i * 256;
            int k   = idx >> 5;
            int j4  = idx & 31;
            *(float4*)&Ws[k * 128 + j4 * 4] =
                *(const float4*)&Wsrc[(size_t)k * ldw + n0 + j4 * 4];
        }
        __syncthreads();

        u64 acc[8][2];
        #pragma unroll
        for (int r = 0; r < 8; r++) { acc[r][0] = 0ULL; acc[r][1] = 0ULL; }

        for (int k4 = 0; k4 < 32; k4++) {
            float4 xv[8];
            #pragma unroll
            for (int r = 0; r < 8; r++)
                xv[r] = *(const float4*)&Xs[(r0 + r) * 132 + k4 * 4];
            #pragma unroll
            for (int kk = 0; kk < 4; kk++) {
                ulonglong2 wv = *(const ulonglong2*)&Ws[(k4 * 4 + kk) * 128 + c0];
                #pragma unroll
                for (int r = 0; r < 8; r++) {
                    float xs = (kk == 0) ? xv[r].x : (kk == 1) ? xv[r].y
                             : (kk == 2) ? xv[r].z : xv[r].w;
                    u64 xp = splat2(xs);
                    fma2(acc[r][0], xp, wv.x);
                    fma2(acc[r][1], xp, wv.y);
                }
            }
        }

        if (nt < 2) {
            float4 bv = *(const float4*)&bg[n0 + c0];
            #pragma unroll
            for (int r = 0; r < 8; r++) {
                float2 a0 = unpack2(acc[r][0]), a1 = unpack2(acc[r][1]);
                float4 o = make_float4(a0.x + bv.x, a0.y + bv.y,
                                       a1.x + bv.z, a1.y + bv.w);
                *(float4*)&g_Xg[(size_t)(m0 + r0 + r) * 256 + n0 + c0] = o;
            }
        } else {
            float4 bv = *(const float4*)&bc[c0];
            #pragma unroll
            for (int r = 0; r < 8; r++) {
                float2 a0 = unpack2(acc[r][0]), a1 = unpack2(acc[r][1]);
                float4 o = make_float4(a0.x + bv.x, a0.y + bv.y,
                                       a1.x + bv.z, a1.y + bv.w);
                *(float4*)&g_Xc[(size_t)(m0 + r0 + r) * 128 + c0] = o;
            }
        }
    }
}

// ---------------------------------------------------------------------------
// Kernel B: GRU recurrence. Same row-major structure & math as R7 (725us),
// but 256 THREADS (2 warps/SMSP) with halved per-thread tiles:
//   Phase G: rows r0..r0+3 (r0=(tid>>7)*4), gate cols (cg, cg+1), cg=(tid&127)*2
//   Phase C: rows rc..rc+1 (rc=(tid>>6)*2),  cand cols (cc, cc+1), cc=(tid&63)*2
// All state reads stay warp-broadcast float4; all w reads contiguous.
// ---------------------------------------------------------------------------
__global__ __launch_bounds__(256, 1)
void gru_kernel(const float* __restrict__ Wg,   // [256][256]
                const float* __restrict__ Wc,   // [256][128]
                const int*   __restrict__ seq_len,
                float* __restrict__ out)        // [1024][200][128]
{
    extern __shared__ float sm[];
    float* Wg_s = sm;                      // [128][256] (h-part of W_gate)
    float* Wc_s = Wg_s + 128 * 256;        // [128][128] (h-part of W_cand)
    float* h_s  = Wc_s + 128 * 128;        // [8][132]
    float* rh_s = h_s  + 8 * 132;          // [8][132]
    float* u_s  = rh_s + 8 * 132;          // [8][132]

    const int tid = threadIdx.x;
    const int b0  = blockIdx.x * 8;

    #pragma unroll
    for (int i = 0; i < 32; i++) {
        int idx = tid + i * 256;
        *(float4*)&Wg_s[idx * 4] = *(const float4*)&Wg[128 * 256 + idx * 4];
    }
    #pragma unroll
    for (int i = 0; i < 16; i++) {
        int idx = tid + i * 256;
        *(float4*)&Wc_s[idx * 4] = *(const float4*)&Wc[128 * 128 + idx * 4];
    }
    for (int i = tid; i < 8 * 132; i += 256) h_s[i] = 0.0f;
    __syncthreads();

    // Phase-G tile
    const int r0 = (tid >> 7) * 4;         // 0 or 4
    const int cg = (tid & 127) * 2;        // gate col pair base 0..254
    // Phase-C tile
    const int rc = (tid >> 6) * 2;         // 0,2,4,6 (constant within a warp)
    const int cc = (tid & 63) * 2;         // cand col pair base 0..126

    int slc[2];
    slc[0] = seq_len[b0 + rc + 0];
    slc[1] = seq_len[b0 + rc + 1];

    for (int t = 0; t < TT; t++) {
        // ---- Phase G: gates = sigmoid(xg + h @ Wg_h) -----------------------
        float2 xg[4];
        #pragma unroll
        for (int i = 0; i < 4; i++)
            xg[i] = *(const float2*)&g_Xg[((size_t)(b0 + r0 + i) * TT + t) * 256 + cg];

        u64 acc[4];
        #pragma unroll
        for (int i = 0; i < 4; i++) acc[i] = 0ULL;

        #pragma unroll 4
        for (int k4 = 0; k4 < 32; k4++) {
            float4 hv[4];
            #pragma unroll
            for (int i = 0; i < 4; i++)
                hv[i] = *(const float4*)&h_s[(r0 + i) * 132 + k4 * 4];
            #pragma unroll
            for (int kk = 0; kk < 4; kk++) {
                u64 w = *(const u64*)&Wg_s[(k4 * 4 + kk) * 256 + cg];
                #pragma unroll
                for (int i = 0; i < 4; i++) {
                    float hs = (kk == 0) ? hv[i].x : (kk == 1) ? hv[i].y
                             : (kk == 2) ? hv[i].z : hv[i].w;
                    fma2(acc[i], splat2(hs), w);
                }
            }
        }

        #pragma unroll
        for (int i = 0; i < 4; i++) {
            float2 a = unpack2(acc[i]);
            float gx = sigmoid_f(a.x + xg[i].x);
            float gy = sigmoid_f(a.y + xg[i].y);
            if (cg < 128) {
                float2 h2 = *(const float2*)&h_s[(r0 + i) * 132 + cg];
                float2 rh; rh.x = gx * h2.x; rh.y = gy * h2.y;
                *(float2*)&rh_s[(r0 + i) * 132 + cg] = rh;
            } else {
                float2 g2; g2.x = gx; g2.y = gy;
                *(float2*)&u_s[(r0 + i) * 132 + (cg - 128)] = g2;
            }
        }
        __syncthreads();

        // ---- Phase C: c = tanh(xc + (r*h) @ Wc_h); h update ----------------
        float2 xc[2];
        #pragma unroll
        for (int i = 0; i < 2; i++)
            xc[i] = *(const float2*)&g_Xc[((size_t)(b0 + rc + i) * TT + t) * 128 + cc];

        u64 ac[2];
        ac[0] = 0ULL; ac[1] = 0ULL;

        #pragma unroll 4
        for (int k4 = 0; k4 < 32; k4++) {
            float4 pv[2];
            #pragma unroll
            for (int i = 0; i < 2; i++)
                pv[i] = *(const float4*)&rh_s[(rc + i) * 132 + k4 * 4];
            #pragma unroll
            for (int kk = 0; kk < 4; kk++) {
                u64 w = *(const u64*)&Wc_s[(k4 * 4 + kk) * 128 + cc];
                #pragma unroll
                for (int i = 0; i < 2; i++) {
                    float ps = (kk == 0) ? pv[i].x : (kk == 1) ? pv[i].y
                             : (kk == 2) ? pv[i].z : pv[i].w;
                    fma2(ac[i], splat2(ps), w);
                }
            }
        }

        #pragma unroll
        for (int i = 0; i < 2; i++) {
            float2 a = unpack2(ac[i]);
            float cv0 = tanh_f(a.x + xc[i].x);
            float cv1 = tanh_f(a.y + xc[i].y);
            float2 hh = *(const float2*)&h_s[(rc + i) * 132 + cc];
            float2 uu = *(const float2*)&u_s[(rc + i) * 132 + cc];
            float hn0 = uu.x * hh.x + (1.0f - uu.x) * cv0;
            float hn1 = uu.y * hh.y + (1.0f - uu.y) * cv1;
            bool valid = (t < slc[i]);
            float2 hw, yw;
            hw.x = valid ? hn0 : hh.x;   hw.y = valid ? hn1 : hh.y;
            yw.x = valid ? hn0 : 0.0f;   yw.y = valid ? hn1 : 0.0f;
            *(float2*)&h_s[(rc + i) * 132 + cc] = hw;
            *(float2*)&out[((size_t)(b0 + rc + i) * TT + t) * 128 + cc] = yw;
        }
        __syncthreads();
    }
}

// ---------------------------------------------------------------------------
extern "C" void kernel_launch(void* const* d_in, const int* in_sizes, int n_in,
                              void* d_out, int out_size)
{
    (void)in_sizes; (void)n_in; (void)out_size;
    const float* X   = (const float*)d_in[0];   // item_his_eb [1024,200,128]
    const int*   sq  = (const int*)  d_in[1];   // seq_len [1024]
    const float* Wg  = (const float*)d_in[2];   // W_gate [256,256]
    const float* bg  = (const float*)d_in[3];   // b_gate [256]
    const float* Wc  = (const float*)d_in[4];   // W_cand [256,128]
    const float* bc  = (const float*)d_in[5];   // b_cand [128]
    float* out = (float*)d_out;                 // [1024,200,128]

    const int smemA = (64 * 132 + 128 * 128) * 4;                     // 99328
    const int smemB = (128 * 256 + 128 * 128 + 3 * 8 * 132) * 4;      // 209280
    cudaFuncSetAttribute(precompute_kernel,
                         cudaFuncAttributeMaxDynamicSharedMemorySize, smemA);
    cudaFuncSetAttribute(gru_kernel,
                         cudaFuncAttributeMaxDynamicSharedMemorySize, smemB);

    precompute_kernel<<<3200, 256, smemA>>>(X, Wg, bg, Wc, bc);
    gru_kernel<<<128, 256, smemB>>>(Wg, Wc, sq, out);
}